// round 6
// baseline (speedup 1.0000x reference)
#include <cuda_runtime.h>
#include <cstdint>

// SSIM loss (16,3,512,512) fp32, fused single kernel:
//   s=img1+img2, d=img1-img2 -> 4 conv fields (S, D, <s^2>, <d^2>)
//   separable 11-tap Gaussian; horizontal conv via warp-private shared strips
//   (no block barrier), vertical conv via register ring; packed f32x2 math;
//   deterministic mean; last-arriving block finalizes: out[0] = 1 - mean.

typedef unsigned long long u64;

#define HH 512
#define WW 512
#define BANDS 3
#define RPB 171                     // rows per band: 171+171+170 = 512
#define NBLOCKS 144                 // 48 planes * 3 bands (one wave, 148 SMs)
#define NTH 512                     // 16 warps; 1 output column per thread
#define NW 16
#define NPIX 12582912.0f

__device__ float g_partials[NBLOCKS];
__device__ unsigned g_ctr = 0;      // self-resetting via atomicInc wrap

// ---------- f32x2 packed helpers (sm_103a) ----------
__device__ __forceinline__ u64 pack2(float lo, float hi) {
    u64 r; asm("mov.b64 %0,{%1,%2};" : "=l"(r) : "f"(lo), "f"(hi)); return r;
}
__device__ __forceinline__ void unpack2(float& lo, float& hi, u64 v) {
    asm("mov.b64 {%0,%1},%2;" : "=f"(lo), "=f"(hi) : "l"(v));
}
__device__ __forceinline__ u64 fma2(u64 a, u64 b, u64 c) {
    u64 d; asm("fma.rn.f32x2 %0,%1,%2,%3;" : "=l"(d) : "l"(a), "l"(b), "l"(c)); return d;
}
__device__ __forceinline__ u64 mul2(u64 a, u64 b) {
    u64 d; asm("mul.rn.f32x2 %0,%1,%2;" : "=l"(d) : "l"(a), "l"(b)); return d;
}

// 1D gaussian, sigma=1.5, window 11, normalized (symmetric: KW(k)=KW(10-k)).
__device__ __forceinline__ constexpr float KW(int k) {
    constexpr float w[6] = {0.00102838f, 0.00759876f, 0.03600077f,
                            0.10936069f, 0.21300554f, 0.26601173f};
    return w[k < 6 ? k : 10 - k];
}

__global__ void __launch_bounds__(NTH, 1)
ssim_main(const float* __restrict__ img1, const float* __restrict__ img2,
          float* __restrict__ out) {
    // Per-warp staging: 48 cols (strip-6 .. strip+41) of (s,d), double-buffered.
    __shared__ float2 srow[NW][2][48];
    __shared__ float wred[NW];
    __shared__ float fin[256];
    __shared__ int is_last;

    const int bx    = blockIdx.x;
    const int plane = bx / BANDS;
    const int band  = bx % BANDS;
    const int y0    = band * RPB;
    const int R     = min(RPB, HH - y0);

    const int t = threadIdx.x;
    const int w = t >> 5;
    const int l = t & 31;
    const int strip0 = w * 32;            // first output col of this warp

    // Staging lanes 0..23 each load a float2 col-pair (cb, cb+1) per image.
    const int cb = strip0 - 6 + 2 * l;
    const bool ldact = (l < 24) && (cb >= 0) && (cb < WW);
    const float* p1 = img1 + (size_t)plane * HH * WW + cb;
    const float* p2 = img2 + (size_t)plane * HH * WW + cb;

    u64 wp[6];
    #pragma unroll
    for (int k = 0; k < 6; k++) wp[k] = pack2(KW(k), KW(k));

    // Vertical ring: per staged row, packed (S,D) and (S2,D2).
    u64 ring[11][2];

    // Row loader (zeros outside the image or for inactive lanes).
    auto ldrow = [&](int rs) -> float4 {
        if (ldact && (unsigned)rs < (unsigned)HH) {
            float2 a = *reinterpret_cast<const float2*>(p1 + (size_t)rs * WW);
            float2 b = *reinterpret_cast<const float2*>(p2 + (size_t)rs * WW);
            return make_float4(a.x, a.y, b.x, b.y);
        }
        return make_float4(0.f, 0.f, 0.f, 0.f);
    };

    int rs = y0 - 5;                      // next row to stage
    float4 pre0 = ldrow(rs);              // 2-deep global prefetch
    float4 pre1 = ldrow(rs + 1);
    float sum = 0.f;

    // Iteration u stages row y0-5+u into ring slot u%11; u>=10 emits row u-10.
    const int UMAX = R + 10;
    int u = 0;
    for (int chunk = 0; chunk < 17 && u < UMAX; chunk++) {
        #pragma unroll
        for (int j = 0; j < 11; j++) {
            if (u >= UMAX) break;
            const int buf = u & 1;

            // ---- stage: compute (s,d) for 2 cols, store to warp strip ----
            {
                float4 cur = pre0;
                pre0 = pre1;
                pre1 = ldrow(rs + 2);
                rs++;
                if (l < 24) {
                    srow[w][buf][2 * l]     = make_float2(cur.x + cur.z, cur.x - cur.z);
                    srow[w][buf][2 * l + 1] = make_float2(cur.y + cur.w, cur.y - cur.w);
                }
            }
            __syncwarp();

            // ---- horizontal 11-tap conv (stride-1 LDS.64, [reg+imm]) ----
            {
                const u64* sp = reinterpret_cast<const u64*>(&srow[w][buf][l + 1]);
                u64 av = 0, aq = 0;
                #pragma unroll
                for (int m = 0; m < 11; m++) {
                    u64 v  = sp[m];
                    u64 q  = mul2(v, v);
                    u64 wt = wp[m < 6 ? m : 10 - m];
                    av = fma2(v, wt, av);
                    aq = fma2(q, wt, aq);
                }
                ring[j][0] = av;          // slot u%11 == j
                ring[j][1] = aq;
            }

            // ---- vertical conv + SSIM for output row u-10 ----
            if (u >= 10) {
                u64 mv = 0, mq = 0;
                #pragma unroll
                for (int k = 0; k < 11; k++) {
                    const int q = (j + 1 + k) % 11;   // compile-time
                    u64 wt = wp[k < 6 ? k : 10 - k];
                    mv = fma2(ring[q][0], wt, mv);
                    mq = fma2(ring[q][1], wt, mq);
                }
                float muS, muD, S2, D2;
                unpack2(muS, muD, mv);
                unpack2(S2, D2, mq);
                float ms2  = muS * muS, md2 = muD * muD;
                float mu12 = 0.25f * (ms2 - md2);            // mu1*mu2
                float musq = 0.5f  * (ms2 + md2);            // mu1^2+mu2^2
                float s12  = fmaf(0.25f, S2 - D2, -mu12);    // sigma12
                float ssq  = fmaf(0.5f,  S2 + D2, -musq);    // s1^2+s2^2
                float num  = fmaf(2.f, mu12, 1e-4f) * fmaf(2.f, s12, 9e-4f);
                float den  = (musq + 1e-4f) * (ssq + 9e-4f);
                sum += __fdividef(num, den);
            }
            u++;
        }
    }

    // ---- deterministic block reduction ----
    #pragma unroll
    for (int o = 16; o > 0; o >>= 1)
        sum += __shfl_down_sync(0xFFFFFFFFu, sum, o);
    if (l == 0) wred[w] = sum;
    __syncthreads();
    if (t == 0) {
        float s = 0.f;
        #pragma unroll
        for (int k = 0; k < NW; k++) s += wred[k];
        g_partials[bx] = s;
        __threadfence();
        unsigned old = atomicInc(&g_ctr, NBLOCKS - 1);   // wraps to 0: self-reset
        is_last = (old == NBLOCKS - 1);
    }
    __syncthreads();

    // ---- last-arriving block finalizes (fixed tree -> deterministic) ----
    if (is_last) {
        __threadfence();   // acquire: all g_partials writes are visible
        if (t < 256)
            fin[t] = (t < NBLOCKS)
                     ? ((const volatile float*)g_partials)[t] : 0.f;
        __syncthreads();
        #pragma unroll
        for (int o = 128; o > 0; o >>= 1) {
            if (t < o) fin[t] += fin[t + o];
            __syncthreads();
        }
        if (t == 0) out[0] = 1.0f - fin[0] * (1.0f / NPIX);
    }
}

extern "C" void kernel_launch(void* const* d_in, const int* in_sizes, int n_in,
                              void* d_out, int out_size) {
    (void)in_sizes; (void)n_in; (void)out_size;
    const float* img1 = (const float*)d_in[0];
    const float* img2 = (const float*)d_in[1];
    float* out = (float*)d_out;

    ssim_main<<<NBLOCKS, NTH>>>(img1, img2, out);
}

// round 10
// speedup vs baseline: 1.3876x; 1.3876x over previous
#include <cuda_runtime.h>
#include <cstdint>

// SSIM loss (16,3,512,512) fp32, fused single kernel.
//   s=img1+img2, d=img1-img2 -> 4 conv fields (S, D, <s^2>, <d^2>)
//   separable 11-tap Gaussian; horizontal conv via warp-private shared strips,
//   vertical conv via register ring (ALL ring indices compile-time: no
//   data-dependent break inside unrolled loops -> no local-memory demotion);
//   packed f32x2 math; deterministic mean; last block finalizes.

typedef unsigned long long u64;

#define HH 512
#define WW 512
#define BANDS 3
#define RPB 171                     // rows per band: 171+171+170 = 512
#define NBLOCKS 144                 // 48 planes * 3 bands (one wave, 148 SMs)
#define NTH 512                     // 16 warps; 1 output column per thread
#define NW 16
#define NCHUNKS 16                  // 16*11 = 176 >= 171 output rows
#define NPIX 12582912.0f

__device__ float g_partials[NBLOCKS];
__device__ unsigned g_ctr = 0;      // self-resetting via atomicInc wrap

// ---------- f32x2 packed helpers (sm_103a) ----------
__device__ __forceinline__ u64 pack2(float lo, float hi) {
    u64 r; asm("mov.b64 %0,{%1,%2};" : "=l"(r) : "f"(lo), "f"(hi)); return r;
}
__device__ __forceinline__ void unpack2(float& lo, float& hi, u64 v) {
    asm("mov.b64 {%0,%1},%2;" : "=f"(lo), "=f"(hi) : "l"(v));
}
__device__ __forceinline__ u64 fma2(u64 a, u64 b, u64 c) {
    u64 d; asm("fma.rn.f32x2 %0,%1,%2,%3;" : "=l"(d) : "l"(a), "l"(b), "l"(c)); return d;
}
__device__ __forceinline__ u64 mul2(u64 a, u64 b) {
    u64 d; asm("mul.rn.f32x2 %0,%1,%2;" : "=l"(d) : "l"(a), "l"(b)); return d;
}

// 1D gaussian, sigma=1.5, window 11, normalized (symmetric: KW(k)=KW(10-k)).
__device__ __forceinline__ constexpr float KW(int k) {
    constexpr float w[6] = {0.00102838f, 0.00759876f, 0.03600077f,
                            0.10936069f, 0.21300554f, 0.26601173f};
    return w[k < 6 ? k : 10 - k];
}

__global__ void __launch_bounds__(NTH, 1)
ssim_main(const float* __restrict__ img1, const float* __restrict__ img2,
          float* __restrict__ out) {
    // Per-warp staging: 48 cols (strip-6 .. strip+41) of (s,d), double-buffered.
    __shared__ float2 srow[NW][2][48];
    __shared__ float wred[NW];
    __shared__ float fin[256];
    __shared__ int is_last;

    const int bx    = blockIdx.x;
    const int plane = bx / BANDS;
    const int band  = bx % BANDS;
    const int y0    = band * RPB;
    const int R     = min(RPB, HH - y0);

    const int t = threadIdx.x;
    const int w = t >> 5;
    const int l = t & 31;
    const int strip0 = w * 32;            // first output col of this warp

    // Staging lanes 0..23 each load a float2 col-pair (cb, cb+1) per image.
    const int cb = strip0 - 6 + 2 * l;
    const bool ldact = (l < 24) && (cb >= 0) && (cb < WW);
    const float* p1 = img1 + (size_t)plane * HH * WW + cb;
    const float* p2 = img2 + (size_t)plane * HH * WW + cb;

    u64 wp[6];
    #pragma unroll
    for (int k = 0; k < 6; k++) wp[k] = pack2(KW(k), KW(k));

    // Vertical ring: per staged row, packed (S,D) and (S2,D2). Register-resident:
    // every index below is a compile-time constant.
    u64 ring[11][2];

    auto ldrow = [&](int r) -> float4 {
        if (ldact && (unsigned)r < (unsigned)HH) {
            float2 a = *reinterpret_cast<const float2*>(p1 + (size_t)r * WW);
            float2 b = *reinterpret_cast<const float2*>(p2 + (size_t)r * WW);
            return make_float4(a.x, a.y, b.x, b.y);
        }
        return make_float4(0.f, 0.f, 0.f, 0.f);
    };

    int rs = y0 - 5;                      // next row to stage
    float4 pre0 = ldrow(rs);              // 3-deep global prefetch
    float4 pre1 = ldrow(rs + 1);
    float4 pre2 = ldrow(rs + 2);
    float sum = 0.f;

    // stage current pre0 into srow[w][buf], advance prefetch.
    auto stage = [&](int buf) {
        float4 cur = pre0;
        pre0 = pre1; pre1 = pre2;
        pre2 = ldrow(rs + 3);
        rs++;
        if (l < 24) {
            srow[w][buf][2 * l]     = make_float2(cur.x + cur.z, cur.x - cur.z);
            srow[w][buf][2 * l + 1] = make_float2(cur.y + cur.w, cur.y - cur.w);
        }
    };

    // horizontal 11-tap conv from srow[w][buf] at this thread's column.
    auto hconv = [&](int buf, u64& av, u64& aq) {
        const u64* sp = reinterpret_cast<const u64*>(&srow[w][buf][l + 1]);
        av = 0; aq = 0;
        #pragma unroll
        for (int m = 0; m < 11; m++) {
            u64 v  = sp[m];
            u64 q  = mul2(v, v);
            u64 wt = wp[m < 6 ? m : 10 - m];
            av = fma2(v, wt, av);
            aq = fma2(q, wt, aq);
        }
    };

    // ---- prologue: stage rows y0-5 .. y0+4 into ring slots 0..9 ----
    #pragma unroll
    for (int j = 0; j < 10; j++) {
        stage(j & 1);
        __syncwarp();
        hconv(j & 1, ring[j][0], ring[j][1]);
    }

    // ---- main: 16 runtime chunks x 11 unrolled iterations, NO breaks ----
    // Iteration (c, j): u = 10 + 11c + j stages into slot (10+j)%11 and emits
    // output row i = 11c + j (discarded when i >= R). Slot math is c-free.
    int bufsel = 0;                       // buf of u=10 is (10&1)=0
    #pragma unroll 1
    for (int c = 0; c < NCHUNKS; c++) {
        const int ibase = 11 * c;
        #pragma unroll
        for (int j = 0; j < 11; j++) {
            stage(bufsel);
            __syncwarp();
            hconv(bufsel, ring[(10 + j) % 11][0], ring[(10 + j) % 11][1]);
            bufsel ^= 1;

            u64 mv = 0, mq = 0;
            #pragma unroll
            for (int k = 0; k < 11; k++) {
                const int q = (j + k) % 11;       // compile-time
                u64 wt = wp[k < 6 ? k : 10 - k];
                mv = fma2(ring[q][0], wt, mv);
                mq = fma2(ring[q][1], wt, mq);
            }
            float muS, muD, S2, D2;
            unpack2(muS, muD, mv);
            unpack2(S2, D2, mq);
            float ms2  = muS * muS, md2 = muD * muD;
            float mu12 = 0.25f * (ms2 - md2);            // mu1*mu2
            float musq = 0.5f  * (ms2 + md2);            // mu1^2+mu2^2
            float s12  = fmaf(0.25f, S2 - D2, -mu12);    // sigma12
            float ssq  = fmaf(0.5f,  S2 + D2, -musq);    // s1^2+s2^2
            float num  = fmaf(2.f, mu12, 1e-4f) * fmaf(2.f, s12, 9e-4f);
            float den  = (musq + 1e-4f) * (ssq + 9e-4f);
            float v    = __fdividef(num, den);
            if (ibase + j < R) sum += v;      // warp-uniform predicate
        }
    }

    // ---- deterministic block reduction ----
    #pragma unroll
    for (int o = 16; o > 0; o >>= 1)
        sum += __shfl_down_sync(0xFFFFFFFFu, sum, o);
    if (l == 0) wred[w] = sum;
    __syncthreads();
    if (t == 0) {
        float s = 0.f;
        #pragma unroll
        for (int k = 0; k < NW; k++) s += wred[k];
        g_partials[bx] = s;
        __threadfence();
        unsigned old = atomicInc(&g_ctr, NBLOCKS - 1);   // wraps to 0: self-reset
        is_last = (old == NBLOCKS - 1);
    }
    __syncthreads();

    // ---- last-arriving block finalizes (fixed tree -> deterministic) ----
    if (is_last) {
        __threadfence();   // acquire: all g_partials writes visible
        if (t < 256)
            fin[t] = (t < NBLOCKS)
                     ? ((const volatile float*)g_partials)[t] : 0.f;
        __syncthreads();
        #pragma unroll
        for (int o = 128; o > 0; o >>= 1) {
            if (t < o) fin[t] += fin[t + o];
            __syncthreads();
        }
        if (t == 0) out[0] = 1.0f - fin[0] * (1.0f / NPIX);
    }
}

extern "C" void kernel_launch(void* const* d_in, const int* in_sizes, int n_in,
                              void* d_out, int out_size) {
    (void)in_sizes; (void)n_in; (void)out_size;
    const float* img1 = (const float*)d_in[0];
    const float* img2 = (const float*)d_in[1];
    float* out = (float*)d_out;

    ssim_main<<<NBLOCKS, NTH>>>(img1, img2, out);
}